// round 4
// baseline (speedup 1.0000x reference)
#include <cuda_runtime.h>
#include <math.h>

// Problem constants
#define Bb   2
#define Tt   2048
#define Vv   32000
#define Dd   1024
#define Ff   256
#define NLl  6
#define LATl 64
#define Mrows (Bb*Tt)          // 4096 token rows

// ---------------- scratch (static __device__, no allocs) ----------------
__device__ float g_h[Mrows*Dd];        // residual stream
__device__ float g_xn[Mrows*Dd];       // layernorm output
__device__ float g_u[Mrows*Dd];        // gated input
__device__ float g_y[Mrows*Dd];        // spec_out result
__device__ float g_concept[Mrows*Dd];  // VIB decoder output
__device__ float g_buf1[Mrows*4*Dd];   // big scratch: gate/ogate pre, ffn hidden
__device__ float g_sp[Mrows*2*Ff];     // spectral input (u_r|u_i)
__device__ float g_ycat[Mrows*2*Ff];   // scan output (y_r|y_i)
__device__ float g_decay[Mrows*Ff];    // sigmoid(decay pre)
__device__ float g_params[Mrows*2*LATl]; // mu|logvar
__device__ float g_accum;              // KL sum

// ---------------- helpers ----------------
__inline__ __device__ float warpsum(float v) {
#pragma unroll
    for (int o = 16; o > 0; o >>= 1) v += __shfl_xor_sync(0xffffffffu, v, o);
    return v;
}

__inline__ __device__ float sigmoidf_(float x) { return 1.0f / (1.0f + expf(-x)); }
__inline__ __device__ float geluf_(float x) { return 0.5f * x * (1.0f + erff(x * 0.70710678118654752f)); }

// ---------------- embed ----------------
__global__ void embed_kernel(const int* __restrict__ x, const float* __restrict__ emb) {
    int row = blockIdx.x;
    int tok = x[row];
    size_t src = (size_t)tok * Dd, dst = (size_t)row * Dd;
#pragma unroll
    for (int i = 0; i < 4; i++) {
        int c = threadIdx.x + i * 256;
        g_h[dst + c] = emb[src + c];
    }
}

// ---------------- layernorm (optionally in + in2) ----------------
__global__ void __launch_bounds__(256) layernorm_kernel(
    const float* __restrict__ in, const float* __restrict__ in2,
    const float* __restrict__ g, const float* __restrict__ bb,
    float* __restrict__ out)
{
    int row = blockIdx.x;
    size_t base = (size_t)row * Dd;
    float vals[4];
    float s = 0.f, s2 = 0.f;
#pragma unroll
    for (int i = 0; i < 4; i++) {
        int c = threadIdx.x + i * 256;
        float v = in[base + c];
        if (in2) v += in2[base + c];
        vals[i] = v; s += v; s2 += v * v;
    }
    __shared__ float sh1[8], sh2[8];
    s = warpsum(s); s2 = warpsum(s2);
    int w = threadIdx.x >> 5, l = threadIdx.x & 31;
    if (l == 0) { sh1[w] = s; sh2[w] = s2; }
    __syncthreads();
    if (w == 0) {
        float a = (l < 8) ? sh1[l] : 0.f;
        float b2 = (l < 8) ? sh2[l] : 0.f;
        a = warpsum(a); b2 = warpsum(b2);
        if (l == 0) { sh1[0] = a; sh2[0] = b2; }
    }
    __syncthreads();
    float mean = sh1[0] * (1.f / Dd);
    float var  = sh2[0] * (1.f / Dd) - mean * mean;
    float inv  = rsqrtf(var + 1e-5f);
#pragma unroll
    for (int i = 0; i < 4; i++) {
        int c = threadIdx.x + i * 256;
        out[base + c] = (vals[i] - mean) * inv * g[c] + bb[c];
    }
}

// ---------------- SGEMM: C[m,n] = act( sum_k A[m,k]*B[n,k] + bias[n] ) (+= if addC)
// A: M x K (row stride ldA), B: N x K (packed), C: M x N (packed).
// Requires M%128==0, N%128==0, K%8==0.
__global__ void __launch_bounds__(256) gemm_nt(
    const float* __restrict__ A, const float* __restrict__ B,
    const float* __restrict__ bias, float* __restrict__ C,
    int M, int N, int K, int ldA, int act, int addC)
{
    __shared__ float As[8][128];
    __shared__ float Bs[8][128];
    int tid = threadIdx.x;
    int tx = tid & 15, ty = tid >> 4;
    int rowBase = blockIdx.y * 128;
    int colBase = blockIdx.x * 128;

    float acc[8][8];
#pragma unroll
    for (int i = 0; i < 8; i++)
#pragma unroll
        for (int j = 0; j < 8; j++) acc[i][j] = 0.f;

    int ra = tid >> 1;           // 0..127 tile row
    int ka = (tid & 1) * 4;      // 0 or 4
    const float* Ap = A + (size_t)(rowBase + ra) * ldA + ka;
    const float* Bp = B + (size_t)(colBase + ra) * K + ka;

    for (int k0 = 0; k0 < K; k0 += 8) {
        float4 av = *(const float4*)(Ap + k0);
        float4 bv = *(const float4*)(Bp + k0);
        As[ka + 0][ra] = av.x; As[ka + 1][ra] = av.y;
        As[ka + 2][ra] = av.z; As[ka + 3][ra] = av.w;
        Bs[ka + 0][ra] = bv.x; Bs[ka + 1][ra] = bv.y;
        Bs[ka + 2][ra] = bv.z; Bs[ka + 3][ra] = bv.w;
        __syncthreads();
#pragma unroll
        for (int kk = 0; kk < 8; kk++) {
            float a[8], b[8];
#pragma unroll
            for (int i = 0; i < 8; i++) a[i] = As[kk][ty * 8 + i];
#pragma unroll
            for (int j = 0; j < 8; j++) b[j] = Bs[kk][tx * 8 + j];
#pragma unroll
            for (int i = 0; i < 8; i++)
#pragma unroll
                for (int j = 0; j < 8; j++) acc[i][j] += a[i] * b[j];
        }
        __syncthreads();
    }

#pragma unroll
    for (int i = 0; i < 8; i++) {
        int r = rowBase + ty * 8 + i;
#pragma unroll
        for (int j = 0; j < 8; j++) {
            int c = colBase + tx * 8 + j;
            float v = acc[i][j];
            if (bias) v += bias[c];
            if (act == 1) v = sigmoidf_(v);
            else if (act == 2) v = geluf_(v);
            size_t idx = (size_t)r * N + c;
            if (addC) C[idx] += v; else C[idx] = v;
        }
    }
}

// ---------------- elementwise ----------------
__global__ void mul_kernel(const float* __restrict__ a, const float* __restrict__ b,
                           float* __restrict__ o, int n) {
    int i = blockIdx.x * blockDim.x + threadIdx.x;
    if (i < n) o[i] = a[i] * b[i];
}

__global__ void fma_add_kernel(float* __restrict__ h, const float* __restrict__ y,
                               const float* __restrict__ s, int n) {
    int i = blockIdx.x * blockDim.x + threadIdx.x;
    if (i < n) h[i] += y[i] * s[i];
}

// ---------------- sequential complex scan over time ----------------
// y_t = a_t * y_{t-1} + u_t  (complex), per (batch, feature) channel.
__global__ void scan_kernel(const float* __restrict__ freq) {
    int tidg = blockIdx.x * blockDim.x + threadIdx.x;
    if (tidg >= Bb * Ff) return;
    int b = tidg / Ff, f = tidg % Ff;
    float w = 0.1f * freq[f];
    float cw = cosf(w), sw = sinf(w);
    float yr = 0.f, yi = 0.f;
    size_t baseF  = (size_t)b * Tt * Ff + f;
    size_t base2F = (size_t)b * Tt * 2 * Ff + f;
    for (int t = 0; t < Tt; t++) {
        float d  = g_decay[baseF + (size_t)t * Ff];
        float ur = g_sp[base2F + (size_t)t * 2 * Ff];
        float ui = g_sp[base2F + (size_t)t * 2 * Ff + Ff];
        float ar = d * cw, ai = d * sw;
        float nyr = ar * yr - ai * yi + ur;
        float nyi = ar * yi + ai * yr + ui;
        yr = nyr; yi = nyi;
        g_ycat[base2F + (size_t)t * 2 * Ff]      = yr;
        g_ycat[base2F + (size_t)t * 2 * Ff + Ff] = yi;
    }
}

// ---------------- KL regularizer ----------------
__global__ void kl_zero_kernel() { g_accum = 0.f; }

__global__ void __launch_bounds__(256) kl_reduce_kernel() {
    int i = blockIdx.x * blockDim.x + threadIdx.x;
    float v = 0.f;
    if (i < Mrows * LATl) {
        int row = i / LATl, l = i % LATl;
        float mu = g_params[(size_t)row * (2 * LATl) + l];
        float lv = g_params[(size_t)row * (2 * LATl) + LATl + l];
        v = -0.5f * (1.f + lv - mu * mu - expf(lv));
    }
    v = warpsum(v);
    __shared__ float sh[8];
    int w = threadIdx.x >> 5, l = threadIdx.x & 31;
    if (l == 0) sh[w] = v;
    __syncthreads();
    if (w == 0) {
        float a = (l < 8) ? sh[l] : 0.f;
        a = warpsum(a);
        if (l == 0) atomicAdd(&g_accum, a);
    }
}

__global__ void kl_final_kernel(float* __restrict__ out, int do_write) {
    if (do_write) {
        float mean = g_accum * (1.f / (float)(Mrows * LATl));
        out[0] = 0.01f * fmaxf(mean, 0.05f);
    }
}

// ---------------- host orchestration ----------------
static void launch_gemm(const float* A, const float* B, const float* bias, float* C,
                        int M, int N, int K, int ldA, int act, int addC) {
    dim3 grid(N / 128, M / 128);
    gemm_nt<<<grid, 256>>>(A, B, bias, C, M, N, K, ldA, act, addC);
}

extern "C" void kernel_launch(void* const* d_in, const int* in_sizes, int n_in,
                              void* d_out, int out_size) {
    (void)in_sizes; (void)n_in;
    const int*   x         = (const int*)  d_in[0];
    const float* emb       = (const float*)d_in[1];
    const float* freq      = (const float*)d_in[2];
    const float* decay_W   = (const float*)d_in[3];
    const float* decay_b   = (const float*)d_in[4];
    const float* spec_in_W = (const float*)d_in[5];
    const float* spec_out_W= (const float*)d_in[6];
    const float* norm1_g   = (const float*)d_in[7];
    const float* norm1_b   = (const float*)d_in[8];
    const float* gate_W    = (const float*)d_in[9];
    const float* gate_b    = (const float*)d_in[10];
    const float* ogate_W   = (const float*)d_in[11];
    const float* ogate_b   = (const float*)d_in[12];
    const float* ffn_g     = (const float*)d_in[13];
    const float* ffn_b     = (const float*)d_in[14];
    const float* ffn_W1    = (const float*)d_in[15];
    const float* ffn_b1    = (const float*)d_in[16];
    const float* ffn_W2    = (const float*)d_in[17];
    const float* ffn_b2    = (const float*)d_in[18];
    const float* vib_g     = (const float*)d_in[19];
    const float* vib_b     = (const float*)d_in[20];
    const float* enc_W     = (const float*)d_in[21];
    const float* enc_b     = (const float*)d_in[22];
    const float* dec_W     = (const float*)d_in[23];
    const float* dec_b     = (const float*)d_in[24];
    const float* normf_g   = (const float*)d_in[25];
    const float* normf_b   = (const float*)d_in[26];
    float* logits = (float*)d_out;

    // resolve scratch symbol addresses (host API, graph-safe, no allocation)
    float *p_h, *p_xn, *p_u, *p_y, *p_concept, *p_buf1, *p_sp, *p_ycat, *p_decay, *p_params;
    cudaGetSymbolAddress((void**)&p_h,       g_h);
    cudaGetSymbolAddress((void**)&p_xn,      g_xn);
    cudaGetSymbolAddress((void**)&p_u,       g_u);
    cudaGetSymbolAddress((void**)&p_y,       g_y);
    cudaGetSymbolAddress((void**)&p_concept, g_concept);
    cudaGetSymbolAddress((void**)&p_buf1,    g_buf1);
    cudaGetSymbolAddress((void**)&p_sp,      g_sp);
    cudaGetSymbolAddress((void**)&p_ycat,    g_ycat);
    cudaGetSymbolAddress((void**)&p_decay,   g_decay);
    cudaGetSymbolAddress((void**)&p_params,  g_params);

    const int NE = Mrows * Dd;                 // 4M elems
    const int EW_BLOCKS = NE / 256;

    // h = emb[x]
    embed_kernel<<<Mrows, 256>>>(x, emb);

    for (int i = 0; i < NLl; i++) {
        const float* gW  = gate_W  + (size_t)i * Dd * Dd;
        const float* ogW = ogate_W + (size_t)i * Dd * Dd;
        const float* dW  = decay_W + (size_t)i * Ff * Dd;
        const float* siW = spec_in_W  + (size_t)i * 2 * Ff * Dd;
        const float* soW = spec_out_W + (size_t)i * Dd * 2 * Ff;
        const float* w1  = ffn_W1 + (size_t)i * 4 * Dd * Dd;
        const float* w2  = ffn_W2 + (size_t)i * Dd * 4 * Dd;

        // xn = LN(h)
        layernorm_kernel<<<Mrows, 256>>>(p_h, nullptr, norm1_g + i * Dd, norm1_b + i * Dd, p_xn);
        // buf1 = sigmoid(xn @ gate_W.T + gate_b)
        launch_gemm(p_xn, gW, gate_b + i * Dd, p_buf1, Mrows, Dd, Dd, Dd, 1, 0);
        // u = xn * buf1
        mul_kernel<<<EW_BLOCKS, 256>>>(p_xn, p_buf1, p_u, NE);
        // decay = sigmoid(u @ decay_W.T + decay_b)
        launch_gemm(p_u, dW, decay_b + i * Ff, p_decay, Mrows, Ff, Dd, Dd, 1, 0);
        // sp = u @ spec_in_W.T
        launch_gemm(p_u, siW, nullptr, p_sp, Mrows, 2 * Ff, Dd, Dd, 0, 0);
        // complex linear recurrence over time
        scan_kernel<<<2, 256>>>(freq + i * Ff);
        // y = ycat @ spec_out_W.T
        launch_gemm(p_ycat, soW, nullptr, p_y, Mrows, Dd, 2 * Ff, 2 * Ff, 0, 0);
        // buf1 = sigmoid(xn @ ogate_W.T + ogate_b)
        launch_gemm(p_xn, ogW, ogate_b + i * Dd, p_buf1, Mrows, Dd, Dd, Dd, 1, 0);
        // h += y * buf1
        fma_add_kernel<<<EW_BLOCKS, 256>>>(p_h, p_y, p_buf1, NE);
        // xn = LN(h) (ffn norm)
        layernorm_kernel<<<Mrows, 256>>>(p_h, nullptr, ffn_g + i * Dd, ffn_b + i * Dd, p_xn);
        // buf1 = gelu(xn @ W1.T + b1)
        launch_gemm(p_xn, w1, ffn_b1 + i * 4 * Dd, p_buf1, Mrows, 4 * Dd, Dd, Dd, 2, 0);
        // h += buf1 @ W2.T + b2
        launch_gemm(p_buf1, w2, ffn_b2 + i * Dd, p_h, Mrows, Dd, 4 * Dd, 4 * Dd, 0, 1);
    }

    // VIB head
    layernorm_kernel<<<Mrows, 256>>>(p_h, nullptr, vib_g, vib_b, p_xn);
    // params = xn @ enc_W.T + enc_b   (N = 2*LAT = 128)
    launch_gemm(p_xn, enc_W, enc_b, p_params, Mrows, 2 * LATl, Dd, Dd, 0, 0);
    // concept = gelu(mu @ dec_W.T + dec_b)  (mu = params[:, :64], ldA = 128, K = 64)
    launch_gemm(p_params, dec_W, dec_b, p_concept, Mrows, Dd, LATl, 2 * LATl, 2, 0);
    // out = LN(h + concept)
    layernorm_kernel<<<Mrows, 256>>>(p_h, p_concept, normf_g, normf_b, p_xn);
    // logits = out @ emb.T
    launch_gemm(p_xn, emb, nullptr, logits, Mrows, Vv, Dd, Dd, 0, 0);

    // reg_loss (written after logits if the output buffer carries it)
    kl_zero_kernel<<<1, 1>>>();
    kl_reduce_kernel<<<(Mrows * LATl + 255) / 256, 256>>>();
    int do_write = (out_size >= Mrows * Vv + 1) ? 1 : 0;
    kl_final_kernel<<<1, 1>>>(logits + (size_t)Mrows * Vv, do_write);
}

// round 10
// speedup vs baseline: 2.5219x; 2.5219x over previous
#include <cuda_runtime.h>
#include <cuda_bf16.h>
#include <math.h>
#include <stdint.h>

#define Bb   2
#define Tt   2048
#define Vv   32000
#define Dd   1024
#define Ff   256
#define NLl  6
#define LATl 64
#define Mrows (Bb*Tt)

// ===== scratch =====
__device__ __align__(128) float g_h[Mrows*Dd];
__device__ __align__(128) float g_xn[Mrows*Dd];
__device__ __align__(128) float g_u[Mrows*Dd];
__device__ __align__(128) float g_buf1[Mrows*4*Dd];
__device__ __align__(128) float g_concept[Mrows*Dd];
__device__ __align__(128) float g_sp[Mrows*2*Ff];
__device__ __align__(128) float g_ycat[Mrows*2*Ff];
__device__ __align__(128) float g_decay[Mrows*Ff];
__device__ __align__(128) float g_params[Mrows*2*LATl];
__device__ float g_accum;

// split-bf16 buffers (K' = 3K)
__device__ __align__(1024) __nv_bfloat16 w_emb3[(size_t)Vv*3*Dd];
__device__ __align__(1024) __nv_bfloat16 w_gate3[(size_t)NLl*Dd*3*Dd];
__device__ __align__(1024) __nv_bfloat16 w_ogate3[(size_t)NLl*Dd*3*Dd];
__device__ __align__(1024) __nv_bfloat16 w_decay3[(size_t)NLl*Ff*3*Dd];
__device__ __align__(1024) __nv_bfloat16 w_specin3[(size_t)NLl*2*Ff*3*Dd];
__device__ __align__(1024) __nv_bfloat16 w_specout3[(size_t)NLl*Dd*3*2*Ff];
__device__ __align__(1024) __nv_bfloat16 w_ffn1_3[(size_t)NLl*4*Dd*3*Dd];
__device__ __align__(1024) __nv_bfloat16 w_ffn2_3[(size_t)NLl*Dd*3*4*Dd];
__device__ __align__(1024) __nv_bfloat16 w_enc3[2*LATl*3*Dd];
__device__ __align__(1024) __nv_bfloat16 w_dec3[Dd*3*LATl];
__device__ __align__(1024) __nv_bfloat16 a_xn3[(size_t)Mrows*3*Dd];
__device__ __align__(1024) __nv_bfloat16 a_u3[(size_t)Mrows*3*Dd];
__device__ __align__(1024) __nv_bfloat16 a_yc3[(size_t)Mrows*3*2*Ff];
__device__ __align__(1024) __nv_bfloat16 a_fh3[(size_t)Mrows*3*4*Dd];
__device__ __align__(1024) __nv_bfloat16 a_mu3[(size_t)Mrows*3*LATl];

// ===== helpers =====
__inline__ __device__ float warpsum(float v) {
#pragma unroll
    for (int o = 16; o > 0; o >>= 1) v += __shfl_xor_sync(0xffffffffu, v, o);
    return v;
}
__device__ __forceinline__ uint32_t smem_u32(const void* p) {
    uint32_t a;
    asm("{ .reg .u64 t; cvta.to.shared.u64 t, %1; cvt.u32.u64 %0, t; }" : "=r"(a) : "l"(p));
    return a;
}
__device__ __forceinline__ void cp16(uint32_t dst, const void* src) {
    asm volatile("cp.async.cg.shared.global [%0], [%1], 16;" :: "r"(dst), "l"(src));
}
__device__ __forceinline__ void cp_commit() { asm volatile("cp.async.commit_group;" ::: "memory"); }
__device__ __forceinline__ void ldm_x4(uint32_t& r0, uint32_t& r1, uint32_t& r2, uint32_t& r3, uint32_t addr) {
    asm volatile("ldmatrix.sync.aligned.m8n8.x4.shared.b16 {%0,%1,%2,%3}, [%4];"
                 : "=r"(r0), "=r"(r1), "=r"(r2), "=r"(r3) : "r"(addr));
}
__device__ __forceinline__ void mma16816(float* c, const uint32_t* a, const uint32_t* b) {
    asm volatile("mma.sync.aligned.m16n8k16.row.col.f32.bf16.bf16.f32 "
                 "{%0,%1,%2,%3}, {%4,%5,%6,%7}, {%8,%9}, {%0,%1,%2,%3};"
                 : "+f"(c[0]), "+f"(c[1]), "+f"(c[2]), "+f"(c[3])
                 : "r"(a[0]), "r"(a[1]), "r"(a[2]), "r"(a[3]), "r"(b[0]), "r"(b[1]));
}

// ===== split3 conversions =====
// A side: [hi | hi | lo].  B side: [hi | lo | hi].  A'.B' = AhBh + AhBl + AlBh
__global__ void split3_A_kernel(const float* __restrict__ in, __nv_bfloat16* __restrict__ out,
                                long n, int K, int ldIn) {
    long i = (long)blockIdx.x * blockDim.x + threadIdx.x;
    if (i >= n) return;
    long m = i / K; int k = (int)(i - m * K);
    float x = in[m * (long)ldIn + k];
    __nv_bfloat16 hi = __float2bfloat16(x);
    __nv_bfloat16 lo = __float2bfloat16(x - __bfloat162float(hi));
    long ob = m * (long)(3 * K);
    out[ob + k] = hi; out[ob + K + k] = hi; out[ob + 2 * K + k] = lo;
}
__global__ void split3_B_kernel(const float* __restrict__ in, __nv_bfloat16* __restrict__ out,
                                long n, int K, int ldIn) {
    long i = (long)blockIdx.x * blockDim.x + threadIdx.x;
    if (i >= n) return;
    long m = i / K; int k = (int)(i - m * K);
    float x = in[m * (long)ldIn + k];
    __nv_bfloat16 hi = __float2bfloat16(x);
    __nv_bfloat16 lo = __float2bfloat16(x - __bfloat162float(hi));
    long ob = m * (long)(3 * K);
    out[ob + k] = hi; out[ob + K + k] = lo; out[ob + 2 * K + k] = hi;
}

// ===== HMMA GEMM: C[m,n] (=|+=) (mul?mul:1)*act(sum_k A[m,k]B[n,k] + bias[n]) =====
// A: Mrows x K bf16, B: N x K bf16, K % 32 == 0, N % 128 == 0.
// 128x128x32 CTA tile, 256 thr, 3-stage cp.async pipeline, warp tile 64x32.
#define ROWB 80                   // padded smem row stride in bytes (32 bf16 -> 80B)
#define TILEB (128*ROWB)          // 10240 bytes per operand tile
#define STGB  (2*TILEB)           // 20480 per stage (A then B)
#define NSTG  3

__global__ void __launch_bounds__(256) gemm_mma(
    const __nv_bfloat16* __restrict__ A, const __nv_bfloat16* __restrict__ B,
    const float* __restrict__ bias, float* __restrict__ C,
    const float* __restrict__ mul, int N, int K, int act, int addC)
{
    extern __shared__ char dsm[];
    const uint32_t sm = smem_u32(dsm);
    const int tid = threadIdx.x;
    const int wid = tid >> 5, lane = tid & 31;
    const int warp_m = wid >> 2;          // 0..1
    const int warp_n = wid & 3;           // 0..3
    const int rowBase = blockIdx.x * 128;
    const int colBase = blockIdx.y * 128;
    const int NC = K >> 5;

    float acc[4][4][4];
#pragma unroll
    for (int i = 0; i < 4; i++)
#pragma unroll
        for (int j = 0; j < 4; j++)
#pragma unroll
            for (int q = 0; q < 4; q++) acc[i][j][q] = 0.f;

    // loader: 512 16B-chunks per operand tile -> 2 per thread per operand
    const int lr = tid >> 2;      // 0..63? no: 256 threads, chunk id = tid + i*256
    (void)lr;
    auto loadTile = [&](int it, int stg) {
        const int k0 = it * 32;
        const uint32_t sbase = sm + stg * STGB;
#pragma unroll
        for (int i = 0; i < 2; i++) {
            int c = tid + i * 256;
            int r = c >> 2, ch = c & 3;
            cp16(sbase + r * ROWB + ch * 16,
                 A + (size_t)(rowBase + r) * K + k0 + ch * 8);
        }
#pragma unroll
        for (int i = 0; i < 2; i++) {
            int c = tid + i * 256;
            int r = c >> 2, ch = c & 3;
            cp16(sbase + TILEB + r * ROWB + ch * 16,
                 B + (size_t)(colBase + r) * K + k0 + ch * 8);
        }
    };

    // per-thread ldmatrix base offsets (within a stage)
    const uint32_t aOff = (uint32_t)((warp_m * 64 + (lane & 15)) * ROWB + (lane >> 4) * 16);
    const uint32_t bOff = (uint32_t)(TILEB +
        (warp_n * 32 + (lane & 7) + ((lane >> 4) & 1) * 8) * ROWB + ((lane >> 3) & 1) * 16);

    loadTile(0, 0); cp_commit();
    loadTile(1, 1); cp_commit();

    for (int it = 0; it < NC; it++) {
        asm volatile("cp.async.wait_group 1;" ::: "memory");
        __syncthreads();
        if (it + 2 < NC) loadTile(it + 2, (it + 2) % NSTG);
        cp_commit();

        const uint32_t sbase = sm + (it % NSTG) * STGB;
#pragma unroll
        for (int ks = 0; ks < 2; ks++) {
            uint32_t a[4][4];
#pragma unroll
            for (int mt = 0; mt < 4; mt++)
                ldm_x4(a[mt][0], a[mt][1], a[mt][2], a[mt][3],
                       sbase + aOff + mt * (16 * ROWB) + ks * 32);
            uint32_t bf[4][2];
#pragma unroll
            for (int np = 0; np < 2; np++) {
                uint32_t r0, r1, r2, r3;
                ldm_x4(r0, r1, r2, r3, sbase + bOff + np * (16 * ROWB) + ks * 32);
                bf[np * 2][0] = r0; bf[np * 2][1] = r1;
                bf[np * 2 + 1][0] = r2; bf[np * 2 + 1][1] = r3;
            }
#pragma unroll
            for (int mt = 0; mt < 4; mt++)
#pragma unroll
                for (int nt = 0; nt < 4; nt++)
                    mma16816(acc[mt][nt], a[mt], bf[nt]);
        }
    }

    // epilogue
    const int gid = lane >> 2, tig = lane & 3;
#pragma unroll
    for (int mt = 0; mt < 4; mt++) {
#pragma unroll
        for (int nt = 0; nt < 4; nt++) {
            int c = colBase + warp_n * 32 + nt * 8 + tig * 2;
            float bv0 = 0.f, bv1 = 0.f;
            if (bias) { bv0 = bias[c]; bv1 = bias[c + 1]; }
#pragma unroll
            for (int half = 0; half < 2; half++) {
                int r = rowBase + warp_m * 64 + mt * 16 + gid + half * 8;
                float v0 = acc[mt][nt][half * 2 + 0] + bv0;
                float v1 = acc[mt][nt][half * 2 + 1] + bv1;
                if (act == 1) {
                    v0 = 1.0f / (1.0f + expf(-v0));
                    v1 = 1.0f / (1.0f + expf(-v1));
                } else if (act == 2) {
                    v0 = 0.5f * v0 * (1.0f + erff(v0 * 0.70710678118654752f));
                    v1 = 0.5f * v1 * (1.0f + erff(v1 * 0.70710678118654752f));
                }
                size_t ix = (size_t)r * N + c;
                if (mul) {
                    float2 mm = *(const float2*)(mul + ix);
                    v0 *= mm.x; v1 *= mm.y;
                }
                if (addC) {
                    float2 o = *(const float2*)(C + ix);
                    v0 += o.x; v1 += o.y;
                }
                float2 w; w.x = v0; w.y = v1;
                *(float2*)(C + ix) = w;
            }
        }
    }
}

// ===== misc kernels =====
__global__ void embed_kernel(const int* __restrict__ x, const float* __restrict__ emb) {
    int row = blockIdx.x;
    int tok = x[row];
    size_t src = (size_t)tok * Dd, dst = (size_t)row * Dd;
#pragma unroll
    for (int i = 0; i < 4; i++) {
        int c = threadIdx.x + i * 256;
        g_h[dst + c] = emb[src + c];
    }
}

__global__ void __launch_bounds__(256) layernorm_kernel(
    const float* __restrict__ in, const float* __restrict__ in2,
    const float* __restrict__ g, const float* __restrict__ bb, float* __restrict__ out)
{
    int row = blockIdx.x;
    size_t base = (size_t)row * Dd;
    float vals[4];
    float s = 0.f, s2 = 0.f;
#pragma unroll
    for (int i = 0; i < 4; i++) {
        int c = threadIdx.x + i * 256;
        float v = in[base + c];
        if (in2) v += in2[base + c];
        vals[i] = v; s += v; s2 += v * v;
    }
    __shared__ float sh1[8], sh2[8];
    s = warpsum(s); s2 = warpsum(s2);
    int w = threadIdx.x >> 5, l = threadIdx.x & 31;
    if (l == 0) { sh1[w] = s; sh2[w] = s2; }
    __syncthreads();
    if (w == 0) {
        float a = (l < 8) ? sh1[l] : 0.f;
        float b2 = (l < 8) ? sh2[l] : 0.f;
        a = warpsum(a); b2 = warpsum(b2);
        if (l == 0) { sh1[0] = a; sh2[0] = b2; }
    }
    __syncthreads();
    float mean = sh1[0] * (1.f / Dd);
    float inv = rsqrtf(sh2[0] * (1.f / Dd) - mean * mean + 1e-5f);
#pragma unroll
    for (int i = 0; i < 4; i++) {
        int c = threadIdx.x + i * 256;
        out[base + c] = (vals[i] - mean) * inv * g[c] + bb[c];
    }
}

// warp-parallel complex scan: one warp per (b,f); 64 steps/lane; Kogge-Stone combine.
__global__ void __launch_bounds__(256) scan2_kernel(const float* __restrict__ freq) {
    int gwarp = (blockIdx.x * blockDim.x + threadIdx.x) >> 5;
    int lane = threadIdx.x & 31;
    if (gwarp >= Bb * Ff) return;
    int b = gwarp >> 8, f = gwarp & 255;
    float w = 0.1f * freq[f];
    float cw = cosf(w), sw = sinf(w);
    const int L = Tt / 32;
    size_t rbase = (size_t)b * Tt + (size_t)lane * L;

    float Ar = 1.f, Ai = 0.f, Ur = 0.f, Ui = 0.f;
    for (int s = 0; s < L; s++) {
        size_t row = rbase + s;
        float dcy = g_decay[row * Ff + f];
        float ur = g_sp[row * (2 * Ff) + f];
        float ui = g_sp[row * (2 * Ff) + Ff + f];
        float ar = dcy * cw, ai = dcy * sw;
        float nAr = ar * Ar - ai * Ai, nAi = ar * Ai + ai * Ar;
        float nUr = ar * Ur - ai * Ui + ur, nUi = ar * Ui + ai * Ur + ui;
        Ar = nAr; Ai = nAi; Ur = nUr; Ui = nUi;
    }
#pragma unroll
    for (int off = 1; off < 32; off <<= 1) {
        float pAr = __shfl_up_sync(0xffffffffu, Ar, off);
        float pAi = __shfl_up_sync(0xffffffffu, Ai, off);
        float pUr = __shfl_up_sync(0xffffffffu, Ur, off);
        float pUi = __shfl_up_sync(0xffffffffu, Ui, off);
        if (lane >= off) {
            float nAr = Ar * pAr - Ai * pAi;
            float nAi = Ar * pAi + Ai * pAr;
            float nUr = Ar * pUr - Ai * pUi + Ur;
            float nUi = Ar * pUi + Ai * pUr + Ui;
            Ar = nAr; Ai = nAi; Ur = nUr; Ui = nUi;
        }
    }
    float Pr = __shfl_up_sync(0xffffffffu, Ur, 1);
    float Pi = __shfl_up_sync(0xffffffffu, Ui, 1);
    if (lane == 0) { Pr = 0.f; Pi = 0.f; }

    float yr = Pr, yi = Pi;
    for (int s = 0; s < L; s++) {
        size_t row = rbase + s;
        float dcy = g_decay[row * Ff + f];
        float ur = g_sp[row * (2 * Ff) + f];
        float ui = g_sp[row * (2 * Ff) + Ff + f];
        float ar = dcy * cw, ai = dcy * sw;
        float nyr = ar * yr - ai * yi + ur;
        float nyi = ar * yi + ai * yr + ui;
        yr = nyr; yi = nyi;
        g_ycat[row * (2 * Ff) + f] = yr;
        g_ycat[row * (2 * Ff) + Ff + f] = yi;
    }
}

__global__ void kl_zero_kernel() { g_accum = 0.f; }
__global__ void __launch_bounds__(256) kl_reduce_kernel() {
    int i = blockIdx.x * blockDim.x + threadIdx.x;
    float v = 0.f;
    if (i < Mrows * LATl) {
        int row = i / LATl, l = i % LATl;
        float mu = g_params[(size_t)row * (2 * LATl) + l];
        float lv = g_params[(size_t)row * (2 * LATl) + LATl + l];
        v = -0.5f * (1.f + lv - mu * mu - expf(lv));
    }
    v = warpsum(v);
    __shared__ float sh[8];
    int w = threadIdx.x >> 5, l = threadIdx.x & 31;
    if (l == 0) sh[w] = v;
    __syncthreads();
    if (w == 0) {
        float a = (l < 8) ? sh[l] : 0.f;
        a = warpsum(a);
        if (l == 0) atomicAdd(&g_accum, a);
    }
}
__global__ void kl_final_kernel(float* __restrict__ out, int do_write) {
    if (do_write) out[0] = 0.01f * fmaxf(g_accum * (1.f / (float)(Mrows * LATl)), 0.05f);
}

// ===== host =====
static void split3A(const float* in, __nv_bfloat16* out, long rows, int K, int ldIn) {
    long n = rows * K;
    split3_A_kernel<<<(unsigned)((n + 255) / 256), 256>>>(in, out, n, K, ldIn);
}
static void split3B(const float* in, __nv_bfloat16* out, long rows, int K, int ldIn) {
    long n = rows * K;
    split3_B_kernel<<<(unsigned)((n + 255) / 256), 256>>>(in, out, n, K, ldIn);
}
static void tc_gemm(const __nv_bfloat16* A, const __nv_bfloat16* B, const float* bias,
                    float* C, const float* mul, int N, int K3, int act, int addC) {
    dim3 grid(Mrows / 128, N / 128);
    gemm_mma<<<grid, 256, NSTG * STGB>>>(A, B, bias, C, mul, N, K3, act, addC);
}

extern "C" void kernel_launch(void* const* d_in, const int* in_sizes, int n_in,
                              void* d_out, int out_size) {
    (void)in_sizes; (void)n_in;
    const int*   x         = (const int*)  d_in[0];
    const float* emb       = (const float*)d_in[1];
    const float* freq      = (const float*)d_in[2];
    const float* decay_W   = (const float*)d_in[3];
    const float* decay_b   = (const float*)d_in[4];
    const float* spec_in_W = (const float*)d_in[5];
    const float* spec_out_W= (const float*)d_in[6];
    const float* norm1_g   = (const float*)d_in[7];
    const float* norm1_b   = (const float*)d_in[8];
    const float* gate_W    = (const float*)d_in[9];
    const float* gate_b    = (const float*)d_in[10];
    const float* ogate_W   = (const float*)d_in[11];
    const float* ogate_b   = (const float*)d_in[12];
    const float* ffn_g     = (const float*)d_in[13];
    const float* ffn_b     = (const float*)d_in[14];
    const float* ffn_W1    = (const float*)d_in[15];
    const float* ffn_b1    = (const float*)d_in[16];
    const float* ffn_W2    = (const float*)d_in[17];
    const float* ffn_b2    = (const float*)d_in[18];
    const float* vib_g     = (const float*)d_in[19];
    const float* vib_b     = (const float*)d_in[20];
    const float* enc_W     = (const float*)d_in[21];
    const float* enc_b     = (const float*)d_in[22];
    const float* dec_W     = (const float*)d_in[23];
    const float* dec_b     = (const float*)d_in[24];
    const float* normf_g   = (const float*)d_in[25];
    const float* normf_b   = (const float*)d_in[26];
    float* logits = (float*)d_out;

    cudaFuncSetAttribute((const void*)gemm_mma,
                         cudaFuncAttributeMaxDynamicSharedMemorySize, NSTG * STGB);

    float *p_h, *p_xn, *p_u, *p_buf1, *p_concept, *p_sp, *p_ycat, *p_decay, *p_params;
    cudaGetSymbolAddress((void**)&p_h, g_h);
    cudaGetSymbolAddress((void**)&p_xn, g_xn);
    cudaGetSymbolAddress((void**)&p_u, g_u);
    cudaGetSymbolAddress((void**)&p_buf1, g_buf1);
    cudaGetSymbolAddress((void**)&p_concept, g_concept);
    cudaGetSymbolAddress((void**)&p_sp, g_sp);
    cudaGetSymbolAddress((void**)&p_ycat, g_ycat);
    cudaGetSymbolAddress((void**)&p_decay, g_decay);
    cudaGetSymbolAddress((void**)&p_params, g_params);

    __nv_bfloat16 *pw_emb, *pw_gate, *pw_ogate, *pw_decay, *pw_si, *pw_so, *pw_f1, *pw_f2, *pw_enc, *pw_dec;
    __nv_bfloat16 *pa_xn, *pa_u, *pa_yc, *pa_fh, *pa_mu;
    cudaGetSymbolAddress((void**)&pw_emb, w_emb3);
    cudaGetSymbolAddress((void**)&pw_gate, w_gate3);
    cudaGetSymbolAddress((void**)&pw_ogate, w_ogate3);
    cudaGetSymbolAddress((void**)&pw_decay, w_decay3);
    cudaGetSymbolAddress((void**)&pw_si, w_specin3);
    cudaGetSymbolAddress((void**)&pw_so, w_specout3);
    cudaGetSymbolAddress((void**)&pw_f1, w_ffn1_3);
    cudaGetSymbolAddress((void**)&pw_f2, w_ffn2_3);
    cudaGetSymbolAddress((void**)&pw_enc, w_enc3);
    cudaGetSymbolAddress((void**)&pw_dec, w_dec3);
    cudaGetSymbolAddress((void**)&pa_xn, a_xn3);
    cudaGetSymbolAddress((void**)&pa_u, a_u3);
    cudaGetSymbolAddress((void**)&pa_yc, a_yc3);
    cudaGetSymbolAddress((void**)&pa_fh, a_fh3);
    cudaGetSymbolAddress((void**)&pa_mu, a_mu3);

    // weight conversions (every call: same input -> same result; graph-safe)
    split3B(emb, pw_emb, Vv, Dd, Dd);
    split3B(gate_W, pw_gate, (long)NLl * Dd, Dd, Dd);
    split3B(ogate_W, pw_ogate, (long)NLl * Dd, Dd, Dd);
    split3B(decay_W, pw_decay, (long)NLl * Ff, Dd, Dd);
    split3B(spec_in_W, pw_si, (long)NLl * 2 * Ff, Dd, Dd);
    split3B(spec_out_W, pw_so, (long)NLl * Dd, 2 * Ff, 2 * Ff);
    split3B(ffn_W1, pw_f1, (long)NLl * 4 * Dd, Dd, Dd);
    split3B(ffn_W2, pw_f2, (long)NLl * Dd, 4 * Dd, 4 * Dd);
    split3B(enc_W, pw_enc, 2 * LATl, Dd, Dd);
    split3B(dec_W, pw_dec, Dd, LATl, LATl);

    embed_kernel<<<Mrows, 256>>>(x, emb);

    for (int i = 0; i < NLl; i++) {
        const __nv_bfloat16* gW = pw_gate + (size_t)i * Dd * 3 * Dd;
        const __nv_bfloat16* oW = pw_ogate + (size_t)i * Dd * 3 * Dd;
        const __nv_bfloat16* dW = pw_decay + (size_t)i * Ff * 3 * Dd;
        const __nv_bfloat16* siW = pw_si + (size_t)i * 2 * Ff * 3 * Dd;
        const __nv_bfloat16* soW = pw_so + (size_t)i * Dd * 3 * 2 * Ff;
        const __nv_bfloat16* w1 = pw_f1 + (size_t)i * 4 * Dd * 3 * Dd;
        const __nv_bfloat16* w2 = pw_f2 + (size_t)i * Dd * 3 * 4 * Dd;

        layernorm_kernel<<<Mrows, 256>>>(p_h, nullptr, norm1_g + i * Dd, norm1_b + i * Dd, p_xn);
        split3A(p_xn, pa_xn, Mrows, Dd, Dd);
        // u = xn * sigmoid(xn@gW.T + b)
        tc_gemm(pa_xn, gW, gate_b + i * Dd, p_u, p_xn, Dd, 3 * Dd, 1, 0);
        split3A(p_u, pa_u, Mrows, Dd, Dd);
        tc_gemm(pa_u, dW, decay_b + i * Ff, p_decay, nullptr, Ff, 3 * Dd, 1, 0);
        tc_gemm(pa_u, siW, nullptr, p_sp, nullptr, 2 * Ff, 3 * Dd, 0, 0);
        scan2_kernel<<<Bb * Ff * 32 / 256, 256>>>(freq + i * Ff);
        split3A(p_ycat, pa_yc, Mrows, 2 * Ff, 2 * Ff);
        // ogate into buf1
        tc_gemm(pa_xn, oW, ogate_b + i * Dd, p_buf1, nullptr, Dd, 3 * Dd, 1, 0);
        // h += (ycat@soW.T) * ogate
        tc_gemm(pa_yc, soW, nullptr, p_h, p_buf1, Dd, 3 * 2 * Ff, 0, 1);
        layernorm_kernel<<<Mrows, 256>>>(p_h, nullptr, ffn_g + i * Dd, ffn_b + i * Dd, p_xn);
        split3A(p_xn, pa_xn, Mrows, Dd, Dd);
        tc_gemm(pa_xn, w1, ffn_b1 + i * 4 * Dd, p_buf1, nullptr, 4 * Dd, 3 * Dd, 2, 0);
        split3A(p_buf1, pa_fh, Mrows, 4 * Dd, 4 * Dd);
        tc_gemm(pa_fh, w2, ffn_b2 + i * Dd, p_h, nullptr, Dd, 3 * 4 * Dd, 0, 1);
    }

    // VIB head
    layernorm_kernel<<<Mrows, 256>>>(p_h, nullptr, vib_g, vib_b, p_xn);
    split3A(p_xn, pa_xn, Mrows, Dd, Dd);
    tc_gemm(pa_xn, pw_enc, enc_b, p_params, nullptr, 2 * LATl, 3 * Dd, 0, 0);
    split3A(p_params, pa_mu, Mrows, LATl, 2 * LATl);
    tc_gemm(pa_mu, pw_dec, dec_b, p_concept, nullptr, Dd, 3 * LATl, 2, 0);
    layernorm_kernel<<<Mrows, 256>>>(p_h, p_concept, normf_g, normf_b, p_xn);
    split3A(p_xn, pa_xn, Mrows, Dd, Dd);
    tc_gemm(pa_xn, pw_emb, nullptr, logits, nullptr, Vv, 3 * Dd, 0, 0);

    kl_zero_kernel<<<1, 1>>>();
    kl_reduce_kernel<<<(Mrows * LATl + 255) / 256, 256>>>();
    int do_write = (out_size >= Mrows * Vv + 1) ? 1 : 0;
    kl_final_kernel<<<1, 1>>>(logits + (size_t)Mrows * Vv, do_write);
}

// round 13
// speedup vs baseline: 3.3293x; 1.3201x over previous
#include <cuda_runtime.h>
#include <cuda_bf16.h>
#include <cuda_fp16.h>
#include <math.h>
#include <stdint.h>

#define Bb   2
#define Tt   2048
#define Vv   32000
#define Dd   1024
#define Ff   256
#define NLl  6
#define LATl 64
#define Mrows (Bb*Tt)

// ===== fp32 scratch =====
__device__ __align__(128) float g_h[Mrows*Dd];
__device__ __align__(128) float g_xn[Mrows*Dd];
__device__ __align__(128) float g_buf1[Mrows*4*Dd];
__device__ __align__(128) float g_concept[Mrows*Dd];
__device__ __align__(128) float g_sp[Mrows*2*Ff];
__device__ __align__(128) float g_decay[Mrows*Ff];
__device__ __align__(128) float g_params[Mrows*2*LATl];
__device__ float g_accum;

// ===== fp16 weights: [hi | lo] layout, row length 2K =====
__device__ __align__(1024) __half w_gate2[(size_t)NLl*Dd*2*Dd];
__device__ __align__(1024) __half w_ogate2[(size_t)NLl*Dd*2*Dd];
__device__ __align__(1024) __half w_decay2[(size_t)NLl*Ff*2*Dd];
__device__ __align__(1024) __half w_si2[(size_t)NLl*2*Ff*2*Dd];
__device__ __align__(1024) __half w_so2[(size_t)NLl*Dd*2*2*Ff];
__device__ __align__(1024) __half w_f12[(size_t)NLl*4*Dd*2*Dd];
__device__ __align__(1024) __half w_f22[(size_t)NLl*Dd*2*4*Dd];
__device__ __align__(1024) __half w_enc2[2*LATl*2*Dd];
__device__ __align__(1024) __half w_dec2[Dd*2*LATl];
// bf16 [hi | lo] for logits path
__device__ __align__(1024) __nv_bfloat16 w_emb2[(size_t)Vv*2*Dd];
__device__ __align__(1024) __nv_bfloat16 a_xnb[(size_t)Mrows*2*Dd];
// fp16 activations (plain hi)
__device__ __align__(1024) __half a_xnh[(size_t)Mrows*Dd];
__device__ __align__(1024) __half a_uh[(size_t)Mrows*Dd];
__device__ __align__(1024) __half a_fh[(size_t)Mrows*4*Dd];
__device__ __align__(1024) __half a_yc[(size_t)Mrows*2*Ff];
__device__ __align__(1024) __half a_muh[(size_t)Mrows*LATl];

// ===== helpers =====
__inline__ __device__ float warpsum(float v) {
#pragma unroll
    for (int o = 16; o > 0; o >>= 1) v += __shfl_xor_sync(0xffffffffu, v, o);
    return v;
}
__device__ __forceinline__ uint32_t smem_u32(const void* p) {
    uint32_t a;
    asm("{ .reg .u64 t; cvta.to.shared.u64 t, %1; cvt.u32.u64 %0, t; }" : "=r"(a) : "l"(p));
    return a;
}
__device__ __forceinline__ void cp16(uint32_t dst, const void* src) {
    asm volatile("cp.async.cg.shared.global [%0], [%1], 16;" :: "r"(dst), "l"(src));
}
__device__ __forceinline__ void cp_commit() { asm volatile("cp.async.commit_group;" ::: "memory"); }
__device__ __forceinline__ void ldm_x4(uint32_t& r0, uint32_t& r1, uint32_t& r2, uint32_t& r3, uint32_t addr) {
    asm volatile("ldmatrix.sync.aligned.m8n8.x4.shared.b16 {%0,%1,%2,%3}, [%4];"
                 : "=r"(r0), "=r"(r1), "=r"(r2), "=r"(r3) : "r"(addr));
}
template<int DT> struct DTT;
template<> struct DTT<0> {
    using T = __half; using T2 = __half2;
    static __device__ __forceinline__ T2 pack(float a, float b) { return __floats2half2_rn(a, b); }
};
template<> struct DTT<1> {
    using T = __nv_bfloat16; using T2 = __nv_bfloat162;
    static __device__ __forceinline__ T2 pack(float a, float b) { return __floats2bfloat162_rn(a, b); }
};
template<int DT>
__device__ __forceinline__ void mma_ti(float* c, const uint32_t* a, const uint32_t* b);
template<>
__device__ __forceinline__ void mma_ti<0>(float* c, const uint32_t* a, const uint32_t* b) {
    asm volatile("mma.sync.aligned.m16n8k16.row.col.f32.f16.f16.f32 "
                 "{%0,%1,%2,%3}, {%4,%5,%6,%7}, {%8,%9}, {%0,%1,%2,%3};"
                 : "+f"(c[0]), "+f"(c[1]), "+f"(c[2]), "+f"(c[3])
                 : "r"(a[0]), "r"(a[1]), "r"(a[2]), "r"(a[3]), "r"(b[0]), "r"(b[1]));
}
template<>
__device__ __forceinline__ void mma_ti<1>(float* c, const uint32_t* a, const uint32_t* b) {
    asm volatile("mma.sync.aligned.m16n8k16.row.col.f32.bf16.bf16.f32 "
                 "{%0,%1,%2,%3}, {%4,%5,%6,%7}, {%8,%9}, {%0,%1,%2,%3};"
                 : "+f"(c[0]), "+f"(c[1]), "+f"(c[2]), "+f"(c[3])
                 : "r"(a[0]), "r"(a[1]), "r"(a[2]), "r"(a[3]), "r"(b[0]), "r"(b[1]));
}

// ===== weight split kernels =====
__global__ void split2_f16_kernel(const float* __restrict__ in, __half* __restrict__ out,
                                  long n, int K) {
    long i = (long)blockIdx.x * blockDim.x + threadIdx.x;
    if (i >= n) return;
    long m = i / K; int k = (int)(i - m * K);
    float x = in[i];
    __half hi = __float2half_rn(x);
    __half lo = __float2half_rn(x - __half2float(hi));
    long ob = m * (long)(2 * K);
    out[ob + k] = hi; out[ob + K + k] = lo;
}
__global__ void split2_bf16_kernel(const float* __restrict__ in, __nv_bfloat16* __restrict__ out,
                                   long n, int K) {
    long i = (long)blockIdx.x * blockDim.x + threadIdx.x;
    if (i >= n) return;
    long m = i / K; int k = (int)(i - m * K);
    float x = in[i];
    __nv_bfloat16 hi = __float2bfloat16(x);
    __nv_bfloat16 lo = __float2bfloat16(x - __bfloat162float(hi));
    long ob = m * (long)(2 * K);
    out[ob + k] = hi; out[ob + K + k] = lo;
}
__global__ void cvt_mu_kernel() {
    int i = blockIdx.x * blockDim.x + threadIdx.x;
    if (i >= Mrows * LATl) return;
    int m = i >> 6, l = i & 63;
    a_muh[i] = __float2half_rn(g_params[(size_t)m * (2 * LATl) + l]);
}

// ===== HMMA GEMM =====
// C[m,n] (=|+=) (mul?mul:1)*act(sum_{k<K} A[m, mapA(k)] B[n, mapB(k)] + bias[n])
// mapX(k) = k - (k >= limX ? subX : 0). Optional Csplit: plain T output (hi only).
#define ROWB 80
#define TILEB (128*ROWB)
#define STGB  (2*TILEB)
#define NSTG  3

template<int DT>
__global__ void __launch_bounds__(256) gemm_mma(
    const typename DTT<DT>::T* __restrict__ A, const typename DTT<DT>::T* __restrict__ B,
    const float* __restrict__ bias, float* __restrict__ C,
    const float* __restrict__ mul, typename DTT<DT>::T* __restrict__ Csplit,
    int N, int K, int ldA, int ldB, int limA, int subA, int limB, int subB,
    int act, int addC)
{
    using T2 = typename DTT<DT>::T2;
    extern __shared__ char dsm[];
    const uint32_t sm = smem_u32(dsm);
    const int tid = threadIdx.x;
    const int wid = tid >> 5, lane = tid & 31;
    const int warp_m = wid >> 2;
    const int warp_n = wid & 3;
    const int rowBase = blockIdx.x * 128;
    const int colBase = blockIdx.y * 128;
    const int NC = K >> 5;

    float acc[4][4][4];
#pragma unroll
    for (int i = 0; i < 4; i++)
#pragma unroll
        for (int j = 0; j < 4; j++)
#pragma unroll
            for (int q = 0; q < 4; q++) acc[i][j][q] = 0.f;

    auto loadTile = [&](int it, int stg) {
        const int k0 = it * 32;
        const int kA = k0 >= limA ? k0 - subA : k0;
        const int kB = k0 >= limB ? k0 - subB : k0;
        const uint32_t sbase = sm + stg * STGB;
#pragma unroll
        for (int i = 0; i < 2; i++) {
            int c = tid + i * 256;
            int r = c >> 2, ch = c & 3;
            cp16(sbase + r * ROWB + ch * 16,
                 A + (size_t)(rowBase + r) * ldA + kA + ch * 8);
        }
#pragma unroll
        for (int i = 0; i < 2; i++) {
            int c = tid + i * 256;
            int r = c >> 2, ch = c & 3;
            cp16(sbase + TILEB + r * ROWB + ch * 16,
                 B + (size_t)(colBase + r) * ldB + kB + ch * 8);
        }
    };

    const uint32_t aOff = (uint32_t)((warp_m * 64 + (lane & 15)) * ROWB + (lane >> 4) * 16);
    const uint32_t bOff = (uint32_t)(TILEB +
        (warp_n * 32 + (lane & 7) + ((lane >> 4) & 1) * 8) * ROWB + ((lane >> 3) & 1) * 16);

    loadTile(0, 0); cp_commit();
    loadTile(1, 1); cp_commit();

    for (int it = 0; it < NC; it++) {
        asm volatile("cp.async.wait_group 1;" ::: "memory");
        __syncthreads();
        if (it + 2 < NC) loadTile(it + 2, (it + 2) % NSTG);
        cp_commit();

        const uint32_t sbase = sm + (it % NSTG) * STGB;
#pragma unroll
        for (int ks = 0; ks < 2; ks++) {
            uint32_t a[4][4];
#pragma unroll
            for (int mt = 0; mt < 4; mt++)
                ldm_x4(a[mt][0], a[mt][1], a[mt][2], a[mt][3],
                       sbase + aOff + mt * (16 * ROWB) + ks * 32);
            uint32_t bf[4][2];
#pragma unroll
            for (int np = 0; np < 2; np++) {
                uint32_t r0, r1, r2, r3;
                ldm_x4(r0, r1, r2, r3, sbase + bOff + np * (16 * ROWB) + ks * 32);
                bf[np * 2][0] = r0; bf[np * 2][1] = r1;
                bf[np * 2 + 1][0] = r2; bf[np * 2 + 1][1] = r3;
            }
#pragma unroll
            for (int mt = 0; mt < 4; mt++)
#pragma unroll
                for (int nt = 0; nt < 4; nt++)
                    mma_ti<DT>(acc[mt][nt], a[mt], bf[nt]);
        }
    }

    const int gid = lane >> 2, tig = lane & 3;
#pragma unroll
    for (int mt = 0; mt < 4; mt++) {
#pragma unroll
        for (int nt = 0; nt < 4; nt++) {
            int c = colBase + warp_n * 32 + nt * 8 + tig * 2;
            float bv0 = 0.f, bv1 = 0.f;
            if (bias) { bv0 = bias[c]; bv1 = bias[c + 1]; }
#pragma unroll
            for (int half = 0; half < 2; half++) {
                int r = rowBase + warp_m * 64 + mt * 16 + gid + half * 8;
                float v0 = acc[mt][nt][half * 2 + 0] + bv0;
                float v1 = acc[mt][nt][half * 2 + 1] + bv1;
                if (act == 1) {
                    v0 = 1.0f / (1.0f + expf(-v0));
                    v1 = 1.0f / (1.0f + expf(-v1));
                } else if (act == 2) {
                    v0 = 0.5f * v0 * (1.0f + erff(v0 * 0.70710678118654752f));
                    v1 = 0.5f * v1 * (1.0f + erff(v1 * 0.70710678118654752f));
                }
                size_t ix = (size_t)r * N + c;
                if (mul) {
                    float2 mm = *(const float2*)(mul + ix);
                    v0 *= mm.x; v1 *= mm.y;
                }
                if (C) {
                    float a0 = v0, a1 = v1;
                    if (addC) {
                        float2 o = *(const float2*)(C + ix);
                        a0 += o.x; a1 += o.y;
                    }
                    float2 w; w.x = a0; w.y = a1;
                    *(float2*)(C + ix) = w;
                }
                if (Csplit) {
                    *reinterpret_cast<T2*>(Csplit + ix) = DTT<DT>::pack(v0, v1);
                }
            }
        }
    }
}

// ===== misc kernels =====
__global__ void embed_kernel(const int* __restrict__ x, const float* __restrict__ emb) {
    int row = blockIdx.x;
    int tok = x[row];
    size_t src = (size_t)tok * Dd, dst = (size_t)row * Dd;
#pragma unroll
    for (int i = 0; i < 4; i++) {
        int c = threadIdx.x + i * 256;
        g_h[dst + c] = emb[src + c];
    }
}

__global__ void __launch_bounds__(256) layernorm_kernel(
    const float* __restrict__ in, const float* __restrict__ in2,
    const float* __restrict__ g, const float* __restrict__ bb,
    float* __restrict__ out, __half* __restrict__ outh)
{
    int row = blockIdx.x;
    size_t base = (size_t)row * Dd;
    float vals[4];
    float s = 0.f, s2 = 0.f;
#pragma unroll
    for (int i = 0; i < 4; i++) {
        int c = threadIdx.x + i * 256;
        float v = in[base + c];
        if (in2) v += in2[base + c];
        vals[i] = v; s += v; s2 += v * v;
    }
    __shared__ float sh1[8], sh2[8];
    s = warpsum(s); s2 = warpsum(s2);
    int w = threadIdx.x >> 5, l = threadIdx.x & 31;
    if (l == 0) { sh1[w] = s; sh2[w] = s2; }
    __syncthreads();
    if (w == 0) {
        float a = (l < 8) ? sh1[l] : 0.f;
        float b2 = (l < 8) ? sh2[l] : 0.f;
        a = warpsum(a); b2 = warpsum(b2);
        if (l == 0) { sh1[0] = a; sh2[0] = b2; }
    }
    __syncthreads();
    float mean = sh1[0] * (1.f / Dd);
    float inv = rsqrtf(sh2[0] * (1.f / Dd) - mean * mean + 1e-5f);
#pragma unroll
    for (int i = 0; i < 4; i++) {
        int c = threadIdx.x + i * 256;
        float v = (vals[i] - mean) * inv * g[c] + bb[c];
        out[base + c] = v;
        if (outh) outh[base + c] = __float2half_rn(v);
    }
}

// warp-parallel complex scan; writes fp16 ycat directly.
__global__ void __launch_bounds__(256) scan2_kernel(const float* __restrict__ freq) {
    int gwarp = (blockIdx.x * blockDim.x + threadIdx.x) >> 5;
    int lane = threadIdx.x & 31;
    if (gwarp >= Bb * Ff) return;
    int b = gwarp >> 8, f = gwarp & 255;
    float w = 0.1f * freq[f];
    float cw = cosf(w), sw = sinf(w);
    const int L = Tt / 32;
    size_t rbase = (size_t)b * Tt + (size_t)lane * L;

    float Ar = 1.f, Ai = 0.f, Ur = 0.f, Ui = 0.f;
    for (int s = 0; s < L; s++) {
        size_t row = rbase + s;
        float dcy = g_decay[row * Ff + f];
        float ur = g_sp[row * (2 * Ff) + f];
        float ui = g_sp[row * (2 * Ff) + Ff + f];
        float ar = dcy * cw, ai = dcy * sw;
        float nAr = ar * Ar - ai * Ai, nAi = ar * Ai + ai * Ar;
        float nUr = ar * Ur - ai * Ui + ur, nUi = ar * Ui + ai * Ur + ui;
        Ar = nAr; Ai = nAi; Ur = nUr; Ui = nUi;
    }
#pragma unroll
    for (int off = 1; off < 32; off <<= 1) {
        float pAr = __shfl_up_sync(0xffffffffu, Ar, off);
        float pAi = __shfl_up_sync(0xffffffffu, Ai, off);
        float pUr = __shfl_up_sync(0xffffffffu, Ur, off);
        float pUi = __shfl_up_sync(0xffffffffu, Ui, off);
        if (lane >= off) {
            float nAr = Ar * pAr - Ai * pAi;
            float nAi = Ar * pAi + Ai * pAr;
            float nUr = Ar * pUr - Ai * pUi + Ur;
            float nUi = Ar * pUi + Ai * pUr + Ui;
            Ar = nAr; Ai = nAi; Ur = nUr; Ui = nUi;
        }
    }
    float Pr = __shfl_up_sync(0xffffffffu, Ur, 1);
    float Pi = __shfl_up_sync(0xffffffffu, Ui, 1);
    if (lane == 0) { Pr = 0.f; Pi = 0.f; }

    float yr = Pr, yi = Pi;
    for (int s = 0; s < L; s++) {
        size_t row = rbase + s;
        float dcy = g_decay[row * Ff + f];
        float ur = g_sp[row * (2 * Ff) + f];
        float ui = g_sp[row * (2 * Ff) + Ff + f];
        float ar = dcy * cw, ai = dcy * sw;
        float nyr = ar * yr - ai * yi + ur;
        float nyi = ar * yi + ai * yr + ui;
        yr = nyr; yi = nyi;
        a_yc[row * (2 * Ff) + f] = __float2half_rn(yr);
        a_yc[row * (2 * Ff) + Ff + f] = __float2half_rn(yi);
    }
}

__global__ void kl_zero_kernel() { g_accum = 0.f; }
__global__ void __launch_bounds__(256) kl_reduce_kernel() {
    int i = blockIdx.x * blockDim.x + threadIdx.x;
    float v = 0.f;
    if (i < Mrows * LATl) {
        int row = i / LATl, l = i % LATl;
        float mu = g_params[(size_t)row * (2 * LATl) + l];
        float lv = g_params[(size_t)row * (2 * LATl) + LATl + l];
        v = -0.5f * (1.f + lv - mu * mu - expf(lv));
    }
    v = warpsum(v);
    __shared__ float sh[8];
    int w = threadIdx.x >> 5, l = threadIdx.x & 31;
    if (l == 0) sh[w] = v;
    __syncthreads();
    if (w == 0) {
        float a = (l < 8) ? sh[l] : 0.f;
        a = warpsum(a);
        if (l == 0) atomicAdd(&g_accum, a);
    }
}
__global__ void kl_final_kernel(float* __restrict__ out, int do_write) {
    if (do_write) out[0] = 0.01f * fmaxf(g_accum * (1.f / (float)(Mrows * LATl)), 0.05f);
}

// ===== host =====
static void wsplit_f16(const float* in, __half* out, long rows, int K) {
    long n = rows * K;
    split2_f16_kernel<<<(unsigned)((n + 255) / 256), 256>>>(in, out, n, K);
}
static void wsplit_bf16(const float* in, __nv_bfloat16* out, long rows, int K) {
    long n = rows * K;
    split2_bf16_kernel<<<(unsigned)((n + 255) / 256), 256>>>(in, out, n, K);
}
// fp16 2-term: A plain [rows x Ka], B [hi|lo] (2Ka); K' = 2Ka
static void gemm_f16(const __half* A, const __half* B, const float* bias, float* C,
                     const float* mul, __half* Csplit, int N, int Ka, int act, int addC) {
    dim3 grid(Mrows / 128, N / 128);
    gemm_mma<0><<<grid, 256, NSTG * STGB>>>(A, B, bias, C, mul, Csplit,
        N, 2 * Ka, Ka, 2 * Ka, Ka, Ka, 1 << 30, 0, act, addC);
}
// bf16 3-term: A [hi|lo] (2Ka), B [hi|lo] (2Ka); K' = 3Ka
static void gemm_bf16_3(const __nv_bfloat16* A, const __nv_bfloat16* B, float* C, int N, int Ka) {
    dim3 grid(Mrows / 128, N / 128);
    gemm_mma<1><<<grid, 256, NSTG * STGB>>>(A, B, nullptr, C, nullptr, nullptr,
        N, 3 * Ka, 2 * Ka, 2 * Ka, Ka, Ka, 2 * Ka, 2 * Ka, 0, 0);
}

extern "C" void kernel_launch(void* const* d_in, const int* in_sizes, int n_in,
                              void* d_out, int out_size) {
    (void)in_sizes; (void)n_in;
    const int*   x         = (const int*)  d_in[0];
    const float* emb       = (const float*)d_in[1];
    const float* freq      = (const float*)d_in[2];
    const float* decay_W   = (const float*)d_in[3];
    const float* decay_b   = (const float*)d_in[4];
    const float* spec_in_W = (const float*)d_in[5];
    const float* spec_out_W= (const float*)d_in[6];
    const float* norm1_g   = (const float*)d_in[7];
    const float* norm1_b   = (const float*)d_in[8];
    const float* gate_W    = (const float*)d_in[9];
    const float* gate_b    = (const float*)d_in[10];
    const float* ogate_W   = (const float*)d_in[11];
    const float* ogate_b   = (const float*)d_in[12];
    const float* ffn_g     = (const float*)d_in[13];
    const float* ffn_b     = (const float*)d_in[14];
    const float* ffn_W1    = (const float*)d_in[15];
    const float* ffn_b1    = (const float*)d_in[16];
    const float* ffn_W2    = (const float*)d_in[17];
    const float* ffn_b2    = (const float*)d_in[18];
    const float* vib_g     = (const float*)d_in[19];
    const float* vib_b     = (const float*)d_in[20];
    const float* enc_W     = (const float*)d_in[21];
    const float* enc_b     = (const float*)d_in[22];
    const float* dec_W     = (const float*)d_in[23];
    const float* dec_b     = (const float*)d_in[24];
    const float* normf_g   = (const float*)d_in[25];
    const float* normf_b   = (const float*)d_in[26];
    float* logits = (float*)d_out;

    cudaFuncSetAttribute((const void*)gemm_mma<0>,
                         cudaFuncAttributeMaxDynamicSharedMemorySize, NSTG * STGB);
    cudaFuncSetAttribute((const void*)gemm_mma<1>,
                         cudaFuncAttributeMaxDynamicSharedMemorySize, NSTG * STGB);

    float *p_h, *p_xn, *p_buf1, *p_concept, *p_sp, *p_decay, *p_params;
    cudaGetSymbolAddress((void**)&p_h, g_h);
    cudaGetSymbolAddress((void**)&p_xn, g_xn);
    cudaGetSymbolAddress((void**)&p_buf1, g_buf1);
    cudaGetSymbolAddress((void**)&p_concept, g_concept);
    cudaGetSymbolAddress((void**)&p_sp, g_sp);
    cudaGetSymbolAddress((void**)&p_decay, g_decay);
    cudaGetSymbolAddress((void**)&p_params, g_params);

    __half *pw_gate, *pw_ogate, *pw_decay, *pw_si, *pw_so, *pw_f1, *pw_f2, *pw_enc, *pw_dec;
    __half *pa_xnh, *pa_uh, *pa_fh, *pa_muh, *pa_yc;
    __nv_bfloat16 *pw_emb, *pa_xnb;
    cudaGetSymbolAddress((void**)&pw_gate, w_gate2);
    cudaGetSymbolAddress((void**)&pw_ogate, w_ogate2);
    cudaGetSymbolAddress((void**)&pw_decay, w_decay2);
    cudaGetSymbolAddress((void**)&pw_si, w_si2);
    cudaGetSymbolAddress((void**)&pw_so, w_so2);
    cudaGetSymbolAddress((void**)&pw_f1, w_f12);
    cudaGetSymbolAddress((void**)&pw_f2, w_f22);
    cudaGetSymbolAddress((void**)&pw_enc, w_enc2);
    cudaGetSymbolAddress((void**)&pw_dec, w_dec2);
    cudaGetSymbolAddress((void**)&pw_emb, w_emb2);
    cudaGetSymbolAddress((void**)&pa_xnb, a_xnb);
    cudaGetSymbolAddress((void**)&pa_xnh, a_xnh);
    cudaGetSymbolAddress((void**)&pa_uh, a_uh);
    cudaGetSymbolAddress((void**)&pa_fh, a_fh);
    cudaGetSymbolAddress((void**)&pa_muh, a_muh);
    cudaGetSymbolAddress((void**)&pa_yc, a_yc);

    // launches 0-2: converts needed by layer-0 gate GEMM (launch #5 = ncu -s 5 target)
    wsplit_bf16(emb, pw_emb, Vv, Dd);                       // 0
    wsplit_f16(gate_W, pw_gate, (long)NLl * Dd, Dd);        // 1
    wsplit_f16(ogate_W, pw_ogate, (long)NLl * Dd, Dd);      // 2
    embed_kernel<<<Mrows, 256>>>(x, emb);                   // 3
    layernorm_kernel<<<Mrows, 256>>>(p_h, nullptr, norm1_g, norm1_b, p_xn, pa_xnh); // 4
    // u = xn * sigmoid(xn@gW.T + b)  (fp16 out only)       // 5 <-- ncu target
    gemm_f16(pa_xnh, pw_gate, gate_b, nullptr, p_xn, pa_uh, Dd, Dd, 1, 0);

    // remaining weight converts
    wsplit_f16(decay_W, pw_decay, (long)NLl * Ff, Dd);
    wsplit_f16(spec_in_W, pw_si, (long)NLl * 2 * Ff, Dd);
    wsplit_f16(spec_out_W, pw_so, (long)NLl * Dd, 2 * Ff);
    wsplit_f16(ffn_W1, pw_f1, (long)NLl * 4 * Dd, Dd);
    wsplit_f16(ffn_W2, pw_f2, (long)NLl * Dd, 4 * Dd);
    wsplit_f16(enc_W, pw_enc, 2 * LATl, Dd);
    wsplit_f16(dec_W, pw_dec, Dd, LATl);

    for (int i = 0; i < NLl; i++) {
        const __half* gW = pw_gate + (size_t)i * Dd * 2 * Dd;
        const __half* oW = pw_ogate + (size_t)i * Dd * 2 * Dd;
        const __half* dW = pw_decay + (size_t)i * Ff * 2 * Dd;
        const __half* siW = pw_si + (size_t)i * 2 * Ff * 2 * Dd;
        const __half* soW = pw_so + (size_t)i * Dd * 2 * 2 * Ff;
        const __half* w1 = pw_f1 + (size_t)i * 4 * Dd * 2 * Dd;
        const __half* w2 = pw_f2 + (size_t)i * Dd * 2 * 4 * Dd;

        if (i > 0) {
            layernorm_kernel<<<Mrows, 256>>>(p_h, nullptr, norm1_g + i * Dd, norm1_b + i * Dd, p_xn, pa_xnh);
            gemm_f16(pa_xnh, gW, gate_b + i * Dd, nullptr, p_xn, pa_uh, Dd, Dd, 1, 0);
        }
        gemm_f16(pa_uh, dW, decay_b + i * Ff, p_decay, nullptr, nullptr, Ff, Dd, 1, 0);
        gemm_f16(pa_uh, siW, nullptr, p_sp, nullptr, nullptr, 2 * Ff, Dd, 0, 0);
        scan2_kernel<<<Bb * Ff * 32 / 256, 256>>>(freq + i * Ff);
        gemm_f16(pa_xnh, oW, ogate_b + i * Dd, p_buf1, nullptr, nullptr, Dd, Dd, 1, 0);
        // h += (ycat@soW.T) * ogate
        gemm_f16(pa_yc, soW, nullptr, p_h, p_buf1, nullptr, Dd, 2 * Ff, 0, 1);
        layernorm_kernel<<<Mrows, 256>>>(p_h, nullptr, ffn_g + i * Dd, ffn_b + i * Dd, p_xn, pa_xnh);
        gemm_f16(pa_xnh, w1, ffn_b1 + i * 4 * Dd, nullptr, nullptr, pa_fh, 4 * Dd, Dd, 2, 0);
        gemm_f16(pa_fh, w2, ffn_b2 + i * Dd, p_h, nullptr, nullptr, Dd, 4 * Dd, 0, 1);
    }

    // VIB head
    layernorm_kernel<<<Mrows, 256>>>(p_h, nullptr, vib_g, vib_b, p_xn, pa_xnh);
    gemm_f16(pa_xnh, pw_enc, enc_b, p_params, nullptr, nullptr, 2 * LATl, Dd, 0, 0);
    cvt_mu_kernel<<<(Mrows * LATl + 255) / 256, 256>>>();
    gemm_f16(pa_muh, pw_dec, dec_b, p_concept, nullptr, nullptr, Dd, LATl, 2, 0);
    layernorm_kernel<<<Mrows, 256>>>(p_h, p_concept, normf_g, normf_b, p_xn, nullptr);
    wsplit_bf16(p_xn, pa_xnb, Mrows, Dd);
    gemm_bf16_3(pa_xnb, pw_emb, logits, Vv, Dd);

    kl_zero_kernel<<<1, 1>>>();
    kl_reduce_kernel<<<(Mrows * LATl + 255) / 256, 256>>>();
    int do_write = (out_size >= Mrows * Vv + 1) ? 1 : 0;
    kl_final_kernel<<<1, 1>>>(logits + (size_t)Mrows * Vv, do_write);
}